// round 11
// baseline (speedup 1.0000x reference)
#include <cuda_runtime.h>
#include <math.h>

namespace {

using u64 = unsigned long long;

constexpr int B      = 4096;
constexpr int NHID   = 512;
constexpr int BR     = 32;
constexpr int NG2    = 1024;
constexpr int WSLICE = NHID * BR;
constexpr int MAXIT  = 2048;
constexpr int NIT0   = 512;          // level-0 items (batch 8, static)

// ---- persistent scratch ----
__device__ int   g_cnt[NG2];         // zeroed by hs_combine each run
__device__ int   g_run[NG2];         // zeroed by hs_combine each run
__device__ int   g_off[NG2 + 1];
__device__ int   g_perm[B];
__device__ int2  g_items[MAXIT];     // {start | count<<16, node}  (L1 then L2)
__device__ int   g_nitems;           // L1+L2 item count
__device__ float g_q0[B];
__device__ float g_q1[B];
__device__ float g_q2[B];

// ---- f32x2 helpers (PTX-only packed FMA) ----
__device__ __forceinline__ u64 fma2(u64 a, u64 b, u64 c) {
    u64 d; asm("fma.rn.f32x2 %0, %1, %2, %3;" : "=l"(d) : "l"(a), "l"(b), "l"(c));
    return d;
}
__device__ __forceinline__ u64 add2(u64 a, u64 b) {
    u64 d; asm("add.rn.f32x2 %0, %1, %2;" : "=l"(d) : "l"(a), "l"(b));
    return d;
}
__device__ __forceinline__ u64 dup2(float x) {
    u64 d; asm("mov.b64 %0, {%1, %1};" : "=l"(d) : "r"(__float_as_uint(x)));
    return d;
}
__device__ __forceinline__ float lo32(u64 a) { return __uint_as_float((unsigned)a); }
__device__ __forceinline__ float hi32(u64 a) { return __uint_as_float((unsigned)(a >> 32)); }

__device__ __forceinline__ int warp_incl_scan(int v) {
    int lane = threadIdx.x & 31;
    #pragma unroll
    for (int o = 1; o < 32; o <<= 1) {
        int n = __shfl_up_sync(0xffffffffu, v, o);
        if (lane >= o) v += n;
    }
    return v;
}

// ================= K1: histogram (grid-wide) =================
__global__ void hs_hist(const int* __restrict__ labels)
{
    int i = blockIdx.x * blockDim.x + threadIdx.x;   // 16 x 256
    atomicAdd(&g_cnt[labels[i] >> 5], 1);
}

// ================= K2: scan + item build (1 block, 1024 threads) ===========
__global__ __launch_bounds__(1024)
void hs_scan()
{
    __shared__ int sA[33];
    __shared__ int sB[33];
    __shared__ int soff[NG2 + 1];
    __shared__ int s_tot1;

    const int tid  = threadIdx.x;
    const int lane = tid & 31;
    const int w    = tid >> 5;

    const int c = g_cnt[tid];

    // scan 1: exclusive group offsets
    {
        int inc = warp_incl_scan(c);
        if (lane == 31) sA[w] = inc;
        __syncthreads();
        if (w == 0) { int t = sA[lane]; int ti = warp_incl_scan(t); sA[lane] = ti - t; }
        __syncthreads();
        int off = inc - c + sA[w];
        soff[tid] = off;
        g_off[tid] = off;
        if (tid == NG2 - 1) { soff[NG2] = off + c; g_off[NG2] = off + c; }
    }
    __syncthreads();
    const int off = soff[tid];

    // scan 2: level-2 item offsets (batch 8 per leaf group)
    const int nit2 = (c + 7) >> 3;
    int ioff2, tot2;
    {
        int inc2 = warp_incl_scan(nit2);
        if (lane == 31) sB[w] = inc2;
        __syncthreads();
        if (w == 0) {
            int t = sB[lane]; int ti = warp_incl_scan(t);
            sB[lane] = ti - t;
            if (lane == 31) sB[32] = ti;
        }
        __syncthreads();
        ioff2 = inc2 - nit2 + sB[w];
        tot2  = sB[32];
    }

    // L1 items (32 groups of 32 leaf groups), batch 8
    if (tid < 32) {
        int st1 = soff[tid * 32];
        int c1  = soff[(tid + 1) * 32] - st1;
        int nit1 = (c1 + 7) >> 3;
        int i1 = warp_incl_scan(nit1);
        int it1off = i1 - nit1;
        int tot1 = __shfl_sync(0xffffffffu, i1, 31);
        if (tid == 0) s_tot1 = tot1;
        for (int k = 0; k < nit1; k++) {
            int cc = min(8, c1 - 8 * k);
            g_items[it1off + k] = make_int2((st1 + 8 * k) | (cc << 16), 1 + tid);
        }
    }
    __syncthreads();
    const int tot1 = s_tot1;

    // L2 items, batch 8
    for (int k = 0; k < nit2; k++) {
        int cc = min(8, c - 8 * k);
        g_items[tot1 + ioff2 + k] = make_int2((off + 8 * k) | (cc << 16), 33 + tid);
    }

    if (tid == 0) g_nitems = tot1 + tot2;
}

// ================= K3: scatter (grid-wide) =================
__global__ void hs_scatter(const int* __restrict__ labels)
{
    int i = blockIdx.x * blockDim.x + threadIdx.x;   // 16 x 256
    int g = labels[i] >> 5;
    int pos = g_off[g] + atomicAdd(&g_run[g], 1);
    g_perm[pos] = i;
}

// ============ main: one warp per item, batch 8, W double-buffered,
// ============ x loaded per-sample to shrink the live register set ==========
__global__ __launch_bounds__(128, 6)
void hs_main(const float* __restrict__ inputs,
             const int*   __restrict__ labels,
             const float* __restrict__ W)
{
    const int lane = threadIdx.x & 31;
    const int cg   = lane & 7;      // 4-column group
    const int hs   = lane >> 3;     // h-stripe within 16-chunk
    const int gw   = (blockIdx.x << 2) + (threadIdx.x >> 5);
    const int nw   = gridDim.x << 2;
    const int nit  = NIT0 + g_nitems;

    for (int it = gw; it < nit; it += nw) {
        int start, count, node;
        bool use_perm;
        if (it < NIT0) { start = it * 8; count = 8; node = 0; use_perm = false; }
        else {
            const int2 t = g_items[it - NIT0];
            start = t.x & 0xffff; count = t.x >> 16; node = t.y;
            use_perm = true;
        }

        int shift;
        float* qdst;
        if (node == 0)      { shift = 10; qdst = g_q0; }
        else if (node < 33) { shift = 5;  qdst = g_q1; }
        else                { shift = 0;  qdst = g_q2; }

        // per-lane sample: lane s (<count) owns sample s; others clamp
        const int pos   = start + ((lane < count) ? lane : (count - 1));
        const int myidx = use_perm ? g_perm[pos] : pos;
        const int mylab = labels[myidx];

        // broadcast the 8 x row offsets to all lanes (once per item)
        int xo[8];
        #pragma unroll
        for (int s = 0; s < 8; s++)
            xo[s] = __shfl_sync(0xffffffffu, myidx, s) * NHID;

        const float* __restrict__ Wn = W + (size_t)node * WSLICE + cg * 4;

        u64 acc0[8], acc1[8];       // (c0,c1),(c2,c3) packed per sample
        #pragma unroll
        for (int s = 0; s < 8; s++) { acc0[s] = 0ull; acc1[s] = 0ull; }

        // software pipeline: W for iteration 0 preloaded
        ulonglong2 wv[4];
        #pragma unroll
        for (int j = 0; j < 4; j++)
            wv[j] = *(const ulonglong2*)&Wn[(hs * 4 + j) * BR];

        #pragma unroll 2
        for (int hb = 0; hb < NHID; hb += 16) {
            const int h0 = hb + hs * 4;

            // prefetch next iteration's W (DRAM-streamed) before the FMAs
            ulonglong2 wn[4];
            const bool more = (hb + 16) < NHID;
            #pragma unroll
            for (int j = 0; j < 4; j++)
                if (more) wn[j] = *(const ulonglong2*)&Wn[(h0 + 16 + j) * BR];

            // per-sample: load x (L2-hot), then its 8 fma2 — keeps live set small,
            // chains across samples stay independent for MLP
            #pragma unroll
            for (int s = 0; s < 8; s++) {
                const float4 xv = *(const float4*)&inputs[xo[s] + h0];
                #pragma unroll
                for (int j = 0; j < 4; j++) {
                    const u64 xd = dup2((&xv.x)[j]);
                    acc0[s] = fma2(wv[j].x, xd, acc0[s]);
                    acc1[s] = fma2(wv[j].y, xd, acc1[s]);
                }
            }
            #pragma unroll
            for (int j = 0; j < 4; j++) wv[j] = wn[j];
        }

        // reduce over the 4 h-stripes (lanes cg, cg+8, cg+16, cg+24)
        #pragma unroll
        for (int o = 8; o <= 16; o <<= 1)
            #pragma unroll
            for (int s = 0; s < 8; s++) {
                acc0[s] = add2(acc0[s], __shfl_xor_sync(0xffffffffu, acc0[s], o));
                acc1[s] = add2(acc1[s], __shfl_xor_sync(0xffffffffu, acc1[s], o));
            }

        // per-sample softmax across the 8 column-group lanes
        #pragma unroll
        for (int s = 0; s < 8; s++) {
            const int st = (__shfl_sync(0xffffffffu, mylab, s) >> shift) & 31; // warp-uniform
            const float a0 = lo32(acc0[s]), a1 = hi32(acc0[s]);
            const float a2 = lo32(acc1[s]), a3 = hi32(acc1[s]);
            float mx = fmaxf(fmaxf(a0, a1), fmaxf(a2, a3));
            #pragma unroll
            for (int o = 1; o < 8; o <<= 1)
                mx = fmaxf(mx, __shfl_xor_sync(0xffffffffu, mx, o));
            float e = __expf(a0 - mx) + __expf(a1 - mx) + __expf(a2 - mx) + __expf(a3 - mx);
            #pragma unroll
            for (int o = 1; o < 8; o <<= 1)
                e += __shfl_xor_sync(0xffffffffu, e, o);
            const float lse = mx + __logf(e);
            // selected logit lives in lane (st>>2) of each 8-lane group
            const int r = st & 3;
            const float v = (r == 0) ? a0 : (r == 1) ? a1 : (r == 2) ? a2 : a3;
            const float sel = __shfl_sync(0xffffffffu, v, (lane & 24) | (st >> 2));
            if (lane == s && lane < count) qdst[myidx] = sel - lse;
        }
    }
}

// ================= combine + reset counters for next replay =================
__global__ void hs_combine(float* __restrict__ out)
{
    int i = blockIdx.x * blockDim.x + threadIdx.x;   // 16 x 256
    out[i] = __expf(g_q0[i] + g_q1[i] + g_q2[i]);
    if (i < NG2)          g_cnt[i] = 0;
    else if (i < 2 * NG2) g_run[i - NG2] = 0;
}

} // namespace

extern "C" void kernel_launch(void* const* d_in, const int* in_sizes, int n_in,
                              void* d_out, int out_size)
{
    const float* inputs = (const float*)d_in[0];
    const int*   labels = (const int*)d_in[1];
    const float* W      = (const float*)d_in[2];
    float*       out    = (float*)d_out;

    hs_hist   <<<16, 256>>>(labels);
    hs_scan   <<<1, 1024>>>();
    hs_scatter<<<16, 256>>>(labels);
    hs_main   <<<888, 128>>>(inputs, labels, W);
    hs_combine<<<16, 256>>>(out);
}

// round 12
// speedup vs baseline: 1.0288x; 1.0288x over previous
#include <cuda_runtime.h>
#include <math.h>

namespace {

using u64 = unsigned long long;

constexpr int B      = 4096;
constexpr int NHID   = 512;
constexpr int BR     = 32;
constexpr int NG2    = 1024;
constexpr int WSLICE = NHID * BR;
constexpr int MAXIT  = 2048;
constexpr int NIT0   = 512;          // level-0 items (batch 8, static)

constexpr int NSTAGE     = 3;
constexpr int STAGE_B    = 4 * 528;  // 16 rows x 128B, +16B pad per 4-row unit = 2112

// ---- persistent scratch ----
__device__ int   g_cnt[NG2];         // zeroed by hs_combine each run
__device__ int   g_run[NG2];         // zeroed by hs_combine each run
__device__ int   g_off[NG2 + 1];
__device__ int   g_perm[B];
__device__ int2  g_items[MAXIT];     // {start | count<<16, node}  (L1 then L2)
__device__ int   g_nitems;           // L1+L2 item count
__device__ float g_q0[B];
__device__ float g_q1[B];
__device__ float g_q2[B];

// ---- f32x2 helpers (PTX-only packed FMA) ----
__device__ __forceinline__ u64 fma2(u64 a, u64 b, u64 c) {
    u64 d; asm("fma.rn.f32x2 %0, %1, %2, %3;" : "=l"(d) : "l"(a), "l"(b), "l"(c));
    return d;
}
__device__ __forceinline__ u64 add2(u64 a, u64 b) {
    u64 d; asm("add.rn.f32x2 %0, %1, %2;" : "=l"(d) : "l"(a), "l"(b));
    return d;
}
__device__ __forceinline__ u64 dup2(float x) {
    u64 d; asm("mov.b64 %0, {%1, %1};" : "=l"(d) : "r"(__float_as_uint(x)));
    return d;
}
__device__ __forceinline__ float lo32(u64 a) { return __uint_as_float((unsigned)a); }
__device__ __forceinline__ float hi32(u64 a) { return __uint_as_float((unsigned)(a >> 32)); }

__device__ __forceinline__ ulonglong2 lds128(unsigned addr) {
    ulonglong2 r;
    asm volatile("ld.shared.v2.u64 {%0, %1}, [%2];" : "=l"(r.x), "=l"(r.y) : "r"(addr));
    return r;
}
__device__ __forceinline__ void cp16(unsigned dst, const void* src) {
    asm volatile("cp.async.ca.shared.global [%0], [%1], 16;" :: "r"(dst), "l"(src));
}
__device__ __forceinline__ void cp_commit() {
    asm volatile("cp.async.commit_group;");
}

__device__ __forceinline__ int warp_incl_scan(int v) {
    int lane = threadIdx.x & 31;
    #pragma unroll
    for (int o = 1; o < 32; o <<= 1) {
        int n = __shfl_up_sync(0xffffffffu, v, o);
        if (lane >= o) v += n;
    }
    return v;
}

// ================= K1: histogram (grid-wide) =================
__global__ void hs_hist(const int* __restrict__ labels)
{
    int i = blockIdx.x * blockDim.x + threadIdx.x;   // 16 x 256
    atomicAdd(&g_cnt[labels[i] >> 5], 1);
}

// ================= K2: scan + item build (1 block, 1024 threads) ===========
__global__ __launch_bounds__(1024)
void hs_scan()
{
    __shared__ int sA[33];
    __shared__ int sB[33];
    __shared__ int soff[NG2 + 1];
    __shared__ int s_tot1;

    const int tid  = threadIdx.x;
    const int lane = tid & 31;
    const int w    = tid >> 5;

    const int c = g_cnt[tid];

    // scan 1: exclusive group offsets
    {
        int inc = warp_incl_scan(c);
        if (lane == 31) sA[w] = inc;
        __syncthreads();
        if (w == 0) { int t = sA[lane]; int ti = warp_incl_scan(t); sA[lane] = ti - t; }
        __syncthreads();
        int off = inc - c + sA[w];
        soff[tid] = off;
        g_off[tid] = off;
        if (tid == NG2 - 1) { soff[NG2] = off + c; g_off[NG2] = off + c; }
    }
    __syncthreads();
    const int off = soff[tid];

    // scan 2: level-2 item offsets (batch 8 per leaf group)
    const int nit2 = (c + 7) >> 3;
    int ioff2, tot2;
    {
        int inc2 = warp_incl_scan(nit2);
        if (lane == 31) sB[w] = inc2;
        __syncthreads();
        if (w == 0) {
            int t = sB[lane]; int ti = warp_incl_scan(t);
            sB[lane] = ti - t;
            if (lane == 31) sB[32] = ti;
        }
        __syncthreads();
        ioff2 = inc2 - nit2 + sB[w];
        tot2  = sB[32];
    }

    // L1 items (32 groups of 32 leaf groups), batch 8
    if (tid < 32) {
        int st1 = soff[tid * 32];
        int c1  = soff[(tid + 1) * 32] - st1;
        int nit1 = (c1 + 7) >> 3;
        int i1 = warp_incl_scan(nit1);
        int it1off = i1 - nit1;
        int tot1 = __shfl_sync(0xffffffffu, i1, 31);
        if (tid == 0) s_tot1 = tot1;
        for (int k = 0; k < nit1; k++) {
            int cc = min(8, c1 - 8 * k);
            g_items[it1off + k] = make_int2((st1 + 8 * k) | (cc << 16), 1 + tid);
        }
    }
    __syncthreads();
    const int tot1 = s_tot1;

    // L2 items, batch 8
    for (int k = 0; k < nit2; k++) {
        int cc = min(8, c - 8 * k);
        g_items[tot1 + ioff2 + k] = make_int2((off + 8 * k) | (cc << 16), 33 + tid);
    }

    if (tid == 0) g_nitems = tot1 + tot2;
}

// ================= K3: scatter (grid-wide) =================
__global__ void hs_scatter(const int* __restrict__ labels)
{
    int i = blockIdx.x * blockDim.x + threadIdx.x;   // 16 x 256
    int g = labels[i] >> 5;
    int pos = g_off[g] + atomicAdd(&g_run[g], 1);
    g_perm[pos] = i;
}

// ====== main: one warp per item, batch 8; W staged via cp.async smem ring ===
__global__ __launch_bounds__(128)
void hs_main(const float* __restrict__ inputs,
             const int*   __restrict__ labels,
             const float* __restrict__ W)
{
    __shared__ __align__(16) unsigned char s_w[4][NSTAGE][STAGE_B];

    const int wid  = threadIdx.x >> 5;
    const int lane = threadIdx.x & 31;
    const int cg   = lane & 7;      // 4-column group
    const int hs   = lane >> 3;     // h-stripe within 16-chunk
    const int gw   = (blockIdx.x << 2) + wid;
    const int nw   = gridDim.x << 2;
    const int nit  = NIT0 + g_nitems;

    const unsigned swbase = (unsigned)__cvta_generic_to_shared(&s_w[wid][0][0]);
    // store side: lane copies 64B; +16B pad per 512B unit
    const unsigned cp_off = lane * 64 + (lane >> 3) * 16;
    // read side: row (hs*4+j) of the 16-row chunk, column group cg
    const unsigned rd_off = hs * 528 + cg * 16;

    for (int it = gw; it < nit; it += nw) {
        int start, count, node;
        bool use_perm;
        if (it < NIT0) { start = it * 8; count = 8; node = 0; use_perm = false; }
        else {
            const int2 t = g_items[it - NIT0];
            start = t.x & 0xffff; count = t.x >> 16; node = t.y;
            use_perm = true;
        }

        int shift;
        float* qdst;
        if (node == 0)      { shift = 10; qdst = g_q0; }
        else if (node < 33) { shift = 5;  qdst = g_q1; }
        else                { shift = 0;  qdst = g_q2; }

        // per-lane sample: lane s (<count) owns sample s; others clamp
        const int pos   = start + ((lane < count) ? lane : (count - 1));
        const int myidx = use_perm ? g_perm[pos] : pos;
        const int mylab = labels[myidx];

        int xo[8];
        #pragma unroll
        for (int s = 0; s < 8; s++)
            xo[s] = __shfl_sync(0xffffffffu, myidx, s) * NHID;

        const float* __restrict__ Wbase = W + (size_t)node * WSLICE;

        // smem ring addrs (rotate by variable, no modulo)
        unsigned sb0 = swbase, sb1 = swbase + STAGE_B, sb2 = swbase + 2 * STAGE_B;

        // prologue: stage 0 and 1 (chunks hb=0,16)
        #pragma unroll
        for (int p = 0; p < 2; p++) {
            const float* g = Wbase + p * 512 + lane * 16;
            const unsigned d = ((p == 0) ? sb0 : sb1) + cp_off;
            #pragma unroll
            for (int k = 0; k < 4; k++) cp16(d + k * 16, g + k * 4);
            cp_commit();
        }

        u64 acc0[8], acc1[8];
        #pragma unroll
        for (int s = 0; s < 8; s++) { acc0[s] = 0ull; acc1[s] = 0ull; }

        #pragma unroll 1
        for (int t = 0; t < 32; t++) {
            asm volatile("cp.async.wait_group 1;" ::: "memory");
            __syncwarp();

            // issue chunk t+2 into the 3rd buffer (overwrites buffer read at t-1)
            if (t + 2 < 32) {
                const float* g = Wbase + (t + 2) * 512 + lane * 16;
                const unsigned d = sb2 + cp_off;
                #pragma unroll
                for (int k = 0; k < 4; k++) cp16(d + k * 16, g + k * 4);
            }
            cp_commit();   // empty group when no cp issued: keeps counting uniform

            // compute chunk t from buffer sb0
            const unsigned a = sb0 + rd_off;
            ulonglong2 wv[4];
            #pragma unroll
            for (int j = 0; j < 4; j++) wv[j] = lds128(a + j * 128);

            const int h0 = t * 16 + hs * 4;
            #pragma unroll
            for (int s = 0; s < 8; s++) {
                const float4 xv = *(const float4*)&inputs[xo[s] + h0];
                #pragma unroll
                for (int j = 0; j < 4; j++) {
                    const u64 xd = dup2((&xv.x)[j]);
                    acc0[s] = fma2(wv[j].x, xd, acc0[s]);
                    acc1[s] = fma2(wv[j].y, xd, acc1[s]);
                }
            }

            // rotate ring
            const unsigned tmp = sb0; sb0 = sb1; sb1 = sb2; sb2 = tmp;
        }
        // drain before next item's prologue rewrites buffers
        asm volatile("cp.async.wait_group 0;" ::: "memory");
        __syncwarp();

        // reduce over the 4 h-stripes (lanes cg, cg+8, cg+16, cg+24)
        #pragma unroll
        for (int o = 8; o <= 16; o <<= 1)
            #pragma unroll
            for (int s = 0; s < 8; s++) {
                acc0[s] = add2(acc0[s], __shfl_xor_sync(0xffffffffu, acc0[s], o));
                acc1[s] = add2(acc1[s], __shfl_xor_sync(0xffffffffu, acc1[s], o));
            }

        // per-sample softmax across the 8 column-group lanes
        #pragma unroll
        for (int s = 0; s < 8; s++) {
            const int st = (__shfl_sync(0xffffffffu, mylab, s) >> shift) & 31; // warp-uniform
            const float a0 = lo32(acc0[s]), a1 = hi32(acc0[s]);
            const float a2 = lo32(acc1[s]), a3 = hi32(acc1[s]);
            float mx = fmaxf(fmaxf(a0, a1), fmaxf(a2, a3));
            #pragma unroll
            for (int o = 1; o < 8; o <<= 1)
                mx = fmaxf(mx, __shfl_xor_sync(0xffffffffu, mx, o));
            float e = __expf(a0 - mx) + __expf(a1 - mx) + __expf(a2 - mx) + __expf(a3 - mx);
            #pragma unroll
            for (int o = 1; o < 8; o <<= 1)
                e += __shfl_xor_sync(0xffffffffu, e, o);
            const float lse = mx + __logf(e);
            // selected logit lives in lane (st>>2) of each 8-lane group
            const int r = st & 3;
            const float v = (r == 0) ? a0 : (r == 1) ? a1 : (r == 2) ? a2 : a3;
            const float sel = __shfl_sync(0xffffffffu, v, (lane & 24) | (st >> 2));
            if (lane == s && lane < count) qdst[myidx] = sel - lse;
        }
    }
}

// ================= combine + reset counters for next replay =================
__global__ void hs_combine(float* __restrict__ out)
{
    int i = blockIdx.x * blockDim.x + threadIdx.x;   // 16 x 256
    out[i] = __expf(g_q0[i] + g_q1[i] + g_q2[i]);
    if (i < NG2)          g_cnt[i] = 0;
    else if (i < 2 * NG2) g_run[i - NG2] = 0;
}

} // namespace

extern "C" void kernel_launch(void* const* d_in, const int* in_sizes, int n_in,
                              void* d_out, int out_size)
{
    const float* inputs = (const float*)d_in[0];
    const int*   labels = (const int*)d_in[1];
    const float* W      = (const float*)d_in[2];
    float*       out    = (float*)d_out;

    hs_hist   <<<16, 256>>>(labels);
    hs_scan   <<<1, 1024>>>();
    hs_scatter<<<16, 256>>>(labels);
    hs_main   <<<592, 128>>>(inputs, labels, W);
    hs_combine<<<16, 256>>>(out);
}

// round 13
// speedup vs baseline: 1.7213x; 1.6732x over previous
#include <cuda_runtime.h>
#include <math.h>

namespace {

using u64 = unsigned long long;

constexpr int B      = 4096;
constexpr int NHID   = 512;
constexpr int BR     = 32;
constexpr int NG2    = 1024;
constexpr int WSLICE = NHID * BR;
constexpr int MAXIT  = 2048;
constexpr int NIT0   = 512;          // level-0 items (batch 8, static)

// ---- persistent scratch ----
__device__ int   g_perm[B];
__device__ int2  g_items[MAXIT];     // {start | count<<16, node}  (L1 then L2)
__device__ int   g_nitems;           // L1+L2 item count
__device__ float g_q0[B];
__device__ float g_q1[B];
__device__ float g_q2[B];

// ---- f32x2 helpers (PTX-only packed FMA) ----
__device__ __forceinline__ u64 fma2(u64 a, u64 b, u64 c) {
    u64 d; asm("fma.rn.f32x2 %0, %1, %2, %3;" : "=l"(d) : "l"(a), "l"(b), "l"(c));
    return d;
}
__device__ __forceinline__ u64 add2(u64 a, u64 b) {
    u64 d; asm("add.rn.f32x2 %0, %1, %2;" : "=l"(d) : "l"(a), "l"(b));
    return d;
}
__device__ __forceinline__ u64 dup2(float x) {
    u64 d; asm("mov.b64 %0, {%1, %1};" : "=l"(d) : "r"(__float_as_uint(x)));
    return d;
}
__device__ __forceinline__ float lo32(u64 a) { return __uint_as_float((unsigned)a); }
__device__ __forceinline__ float hi32(u64 a) { return __uint_as_float((unsigned)(a >> 32)); }

__device__ __forceinline__ int warp_incl_scan(int v) {
    int lane = threadIdx.x & 31;
    #pragma unroll
    for (int o = 1; o < 32; o <<= 1) {
        int n = __shfl_up_sync(0xffffffffu, v, o);
        if (lane >= o) v += n;
    }
    return v;
}

// ========== sort: one block, 1024 threads; all counters in smem ==========
__global__ __launch_bounds__(1024)
void hs_sort(const int* __restrict__ labels)
{
    __shared__ int scnt[NG2];
    __shared__ int soff[NG2 + 1];
    __shared__ int srun[NG2];
    __shared__ int sA[33];
    __shared__ int sB[33];
    __shared__ int s_tot1;

    const int tid  = threadIdx.x;
    const int lane = tid & 31;
    const int w    = tid >> 5;

    scnt[tid] = 0;
    srun[tid] = 0;
    __syncthreads();

    const int4 lab4 = ((const int4*)labels)[tid];
    atomicAdd(&scnt[lab4.x >> 5], 1);
    atomicAdd(&scnt[lab4.y >> 5], 1);
    atomicAdd(&scnt[lab4.z >> 5], 1);
    atomicAdd(&scnt[lab4.w >> 5], 1);
    __syncthreads();

    const int c = scnt[tid];

    // scan 1: exclusive leaf-group offsets
    {
        int inc = warp_incl_scan(c);
        if (lane == 31) sA[w] = inc;
        __syncthreads();
        if (w == 0) { int t = sA[lane]; int ti = warp_incl_scan(t); sA[lane] = ti - t; }
        __syncthreads();
        int off = inc - c + sA[w];
        soff[tid] = off;
        if (tid == NG2 - 1) soff[NG2] = off + c;
    }
    __syncthreads();
    const int off = soff[tid];

    // scan 2: level-2 item offsets (batch 8 per leaf group)
    const int nit2 = (c + 7) >> 3;
    int ioff2, tot2;
    {
        int inc2 = warp_incl_scan(nit2);
        if (lane == 31) sB[w] = inc2;
        __syncthreads();
        if (w == 0) {
            int t = sB[lane]; int ti = warp_incl_scan(t);
            sB[lane] = ti - t;
            if (lane == 31) sB[32] = ti;
        }
        __syncthreads();
        ioff2 = inc2 - nit2 + sB[w];
        tot2  = sB[32];
    }

    // scatter into g_perm
    {
        int i = tid * 4;
        int ga = lab4.x >> 5, gb = lab4.y >> 5, gc = lab4.z >> 5, gd = lab4.w >> 5;
        g_perm[soff[ga] + atomicAdd(&srun[ga], 1)] = i;
        g_perm[soff[gb] + atomicAdd(&srun[gb], 1)] = i + 1;
        g_perm[soff[gc] + atomicAdd(&srun[gc], 1)] = i + 2;
        g_perm[soff[gd] + atomicAdd(&srun[gd], 1)] = i + 3;
    }

    // L1 items (32 groups of 32 leaf groups), batch 8
    if (tid < 32) {
        int st1 = soff[tid * 32];
        int c1  = soff[(tid + 1) * 32] - st1;
        int nit1 = (c1 + 7) >> 3;
        int i1 = warp_incl_scan(nit1);
        int it1off = i1 - nit1;
        int tot1 = __shfl_sync(0xffffffffu, i1, 31);
        if (tid == 0) s_tot1 = tot1;
        for (int k = 0; k < nit1; k++) {
            int cc = min(8, c1 - 8 * k);
            g_items[it1off + k] = make_int2((st1 + 8 * k) | (cc << 16), 1 + tid);
        }
    }
    __syncthreads();
    const int tot1 = s_tot1;

    // L2 items, batch 8
    for (int k = 0; k < nit2; k++) {
        int cc = min(8, c - 8 * k);
        g_items[tot1 + ioff2 + k] = make_int2((off + 8 * k) | (cc << 16), 33 + tid);
    }

    if (tid == 0) g_nitems = tot1 + tot2;
}

// ============ main: one warp per item, batch 8, W double-buffered ===========
__global__ __launch_bounds__(128)
void hs_main(const float* __restrict__ inputs,
             const int*   __restrict__ labels,
             const float* __restrict__ W)
{
    const int lane = threadIdx.x & 31;
    const int cg   = lane & 7;      // 4-column group
    const int hs   = lane >> 3;     // h-stripe within 16-chunk
    const int gw   = (blockIdx.x << 2) + (threadIdx.x >> 5);
    const int nw   = gridDim.x << 2;
    const int nit  = NIT0 + g_nitems;

    for (int it = gw; it < nit; it += nw) {
        int start, count, node;
        bool use_perm;
        if (it < NIT0) { start = it * 8; count = 8; node = 0; use_perm = false; }
        else {
            const int2 t = g_items[it - NIT0];
            start = t.x & 0xffff; count = t.x >> 16; node = t.y;
            use_perm = true;
        }

        int shift;
        float* qdst;
        if (node == 0)      { shift = 10; qdst = g_q0; }
        else if (node < 33) { shift = 5;  qdst = g_q1; }
        else                { shift = 0;  qdst = g_q2; }

        // per-lane sample: lane s (<count) owns sample s; others clamp
        const int pos   = start + ((lane < count) ? lane : (count - 1));
        const int myidx = use_perm ? g_perm[pos] : pos;
        const int mylab = labels[myidx];

        // broadcast the 8 x row offsets to all lanes (once per item)
        int xo[8];
        #pragma unroll
        for (int s = 0; s < 8; s++)
            xo[s] = __shfl_sync(0xffffffffu, myidx, s) * NHID;

        const float* __restrict__ Wn = W + (size_t)node * WSLICE + cg * 4;

        u64 acc0[8], acc1[8];       // (c0,c1),(c2,c3) packed per sample
        #pragma unroll
        for (int s = 0; s < 8; s++) { acc0[s] = 0ull; acc1[s] = 0ull; }

        // software pipeline: W for iteration 0 preloaded
        ulonglong2 wv[4];
        #pragma unroll
        for (int j = 0; j < 4; j++)
            wv[j] = *(const ulonglong2*)&Wn[(hs * 4 + j) * BR];

        #pragma unroll 2
        for (int hb = 0; hb < NHID; hb += 16) {
            const int h0 = hb + hs * 4;

            // prefetch next iteration's W before the FMAs
            ulonglong2 wn[4];
            const bool more = (hb + 16) < NHID;
            #pragma unroll
            for (int j = 0; j < 4; j++)
                if (more) wn[j] = *(const ulonglong2*)&Wn[(h0 + 16 + j) * BR];

            // per-sample: load x, then its 8 fma2 — small live set,
            // chains across samples stay independent for MLP
            #pragma unroll
            for (int s = 0; s < 8; s++) {
                const float4 xv = *(const float4*)&inputs[xo[s] + h0];
                #pragma unroll
                for (int j = 0; j < 4; j++) {
                    const u64 xd = dup2((&xv.x)[j]);
                    acc0[s] = fma2(wv[j].x, xd, acc0[s]);
                    acc1[s] = fma2(wv[j].y, xd, acc1[s]);
                }
            }
            #pragma unroll
            for (int j = 0; j < 4; j++) wv[j] = wn[j];
        }

        // reduce over the 4 h-stripes (lanes cg, cg+8, cg+16, cg+24)
        #pragma unroll
        for (int o = 8; o <= 16; o <<= 1)
            #pragma unroll
            for (int s = 0; s < 8; s++) {
                acc0[s] = add2(acc0[s], __shfl_xor_sync(0xffffffffu, acc0[s], o));
                acc1[s] = add2(acc1[s], __shfl_xor_sync(0xffffffffu, acc1[s], o));
            }

        // per-sample softmax across the 8 column-group lanes
        #pragma unroll
        for (int s = 0; s < 8; s++) {
            const int st = (__shfl_sync(0xffffffffu, mylab, s) >> shift) & 31; // warp-uniform
            const float a0 = lo32(acc0[s]), a1 = hi32(acc0[s]);
            const float a2 = lo32(acc1[s]), a3 = hi32(acc1[s]);
            float mx = fmaxf(fmaxf(a0, a1), fmaxf(a2, a3));
            #pragma unroll
            for (int o = 1; o < 8; o <<= 1)
                mx = fmaxf(mx, __shfl_xor_sync(0xffffffffu, mx, o));
            float e = __expf(a0 - mx) + __expf(a1 - mx) + __expf(a2 - mx) + __expf(a3 - mx);
            #pragma unroll
            for (int o = 1; o < 8; o <<= 1)
                e += __shfl_xor_sync(0xffffffffu, e, o);
            const float lse = mx + __logf(e);
            // selected logit lives in lane (st>>2) of each 8-lane group
            const int r = st & 3;
            const float v = (r == 0) ? a0 : (r == 1) ? a1 : (r == 2) ? a2 : a3;
            const float sel = __shfl_sync(0xffffffffu, v, (lane & 24) | (st >> 2));
            if (lane == s && lane < count) qdst[myidx] = sel - lse;
        }
    }
}

// ================= combine =================
__global__ void hs_combine(float* __restrict__ out)
{
    int i = blockIdx.x * blockDim.x + threadIdx.x;   // 16 x 256
    out[i] = __expf(g_q0[i] + g_q1[i] + g_q2[i]);
}

} // namespace

extern "C" void kernel_launch(void* const* d_in, const int* in_sizes, int n_in,
                              void* d_out, int out_size)
{
    const float* inputs = (const float*)d_in[0];
    const int*   labels = (const int*)d_in[1];
    const float* W      = (const float*)d_in[2];
    float*       out    = (float*)d_out;

    hs_sort   <<<1, 1024>>>(labels);
    hs_main   <<<592, 128>>>(inputs, labels, W);
    hs_combine<<<16, 256>>>(out);
}

// round 14
// speedup vs baseline: 1.8441x; 1.0714x over previous
#include <cuda_runtime.h>
#include <math.h>

namespace {

using u64 = unsigned long long;

constexpr int B      = 4096;
constexpr int NHID   = 512;
constexpr int BR     = 32;
constexpr int WSLICE = NHID * BR;
constexpr int MAXIT  = 2048;
constexpr int NIT0   = 512;          // level-0 items (batch 8, static)
constexpr int SEGSZ  = 256;          // g_perm slots per g1 group (Pois(128), +11 sigma)

// ---- persistent scratch ----
__device__ int   g_perm[32 * SEGSZ];
__device__ int2  g_items[MAXIT];     // {start | count<<16, node}  (L1+L2, unordered)
__device__ int   g_nitems = 0;       // accumulated by hs_sort2, reset by hs_combine
__device__ float g_q0[B];
__device__ float g_q1[B];
__device__ float g_q2[B];

// ---- f32x2 helpers (PTX-only packed FMA) ----
__device__ __forceinline__ u64 fma2(u64 a, u64 b, u64 c) {
    u64 d; asm("fma.rn.f32x2 %0, %1, %2, %3;" : "=l"(d) : "l"(a), "l"(b), "l"(c));
    return d;
}
__device__ __forceinline__ u64 add2(u64 a, u64 b) {
    u64 d; asm("add.rn.f32x2 %0, %1, %2;" : "=l"(d) : "l"(a), "l"(b));
    return d;
}
__device__ __forceinline__ u64 dup2(float x) {
    u64 d; asm("mov.b64 %0, {%1, %1};" : "=l"(d) : "r"(__float_as_uint(x)));
    return d;
}
__device__ __forceinline__ float lo32(u64 a) { return __uint_as_float((unsigned)a); }
__device__ __forceinline__ float hi32(u64 a) { return __uint_as_float((unsigned)(a >> 32)); }

__device__ __forceinline__ int warp_incl_scan(int v) {
    int lane = threadIdx.x & 31;
    #pragma unroll
    for (int o = 1; o < 32; o <<= 1) {
        int n = __shfl_up_sync(0xffffffffu, v, o);
        if (lane >= o) v += n;
    }
    return v;
}

// ===== sort: 32 independent blocks, one per g1 group; segmented perm ======
__global__ __launch_bounds__(256)
void hs_sort2(const int* __restrict__ labels)
{
    __shared__ int scnt[32];
    __shared__ int soff[32];
    __shared__ int srun[32];
    __shared__ int sbase;

    const int tid = threadIdx.x;
    const int b   = blockIdx.x;

    if (tid < 32) { scnt[tid] = 0; srun[tid] = 0; }
    __syncthreads();

    // scan all labels; count own-g1 members per leaf bin
    int4 lab4[4];
    #pragma unroll
    for (int k = 0; k < 4; k++) {
        lab4[k] = ((const int4*)labels)[tid + 256 * k];
        const int* l = &lab4[k].x;
        #pragma unroll
        for (int c = 0; c < 4; c++)
            if ((l[c] >> 10) == b) atomicAdd(&scnt[(l[c] >> 5) & 31], 1);
    }
    __syncthreads();

    // warp 0: exclusive scan of the 32 bins
    if (tid < 32) {
        int c = scnt[tid];
        int inc = warp_incl_scan(c);
        soff[tid] = inc - c;
    }
    __syncthreads();

    // scatter members into this block's perm segment
    #pragma unroll
    for (int k = 0; k < 4; k++) {
        const int i0 = 4 * (tid + 256 * k);
        const int* l = &lab4[k].x;
        #pragma unroll
        for (int c = 0; c < 4; c++)
            if ((l[c] >> 10) == b) {
                int bin = (l[c] >> 5) & 31;
                int pos = soff[bin] + atomicAdd(&srun[bin], 1);
                if (pos < SEGSZ) g_perm[b * SEGSZ + pos] = i0 + c;
            }
    }

    // build items (warp 0 only)
    if (tid < 32) {
        const int c    = scnt[tid];
        const int cend = soff[31] + scnt[31];
        const int c1   = __shfl_sync(0xffffffffu, cend, 0);  // same on all lanes via lane31 value
        // (cend computed per-lane is only valid on lane 31; broadcast it)
        const int c1b  = __shfl_sync(0xffffffffu, soff[31] + scnt[31], 31);
        const int nit1 = (c1b + 7) >> 3;
        const int nitb = (c + 7) >> 3;
        int inc  = warp_incl_scan(nitb);
        const int myoff = inc - nitb;
        const int tot2  = __shfl_sync(0xffffffffu, inc, 31);
        (void)c1;
        if (tid == 0) sbase = atomicAdd(&g_nitems, nit1 + tot2);
        __syncwarp();
        const int base = sbase;

        // L1 items: 8-sample chunks over the whole segment
        for (int k = tid; k < nit1; k += 32) {
            int cc = min(8, c1b - 8 * k);
            g_items[base + k] = make_int2((b * SEGSZ + 8 * k) | (cc << 16), 1 + b);
        }
        // L2 items: this lane's leaf bin
        const int st = b * SEGSZ + soff[tid];
        int o = base + nit1 + myoff;
        for (int k = 0; k < nitb; k++) {
            int cc = min(8, c - 8 * k);
            g_items[o + k] = make_int2((st + 8 * k) | (cc << 16), 33 + b * 32 + tid);
        }
    }
}

// ============ main: one warp per item, batch 8, W double-buffered ===========
__global__ __launch_bounds__(128)
void hs_main(const float* __restrict__ inputs,
             const int*   __restrict__ labels,
             const float* __restrict__ W)
{
    const int lane = threadIdx.x & 31;
    const int cg   = lane & 7;      // 4-column group
    const int hs   = lane >> 3;     // h-stripe within 16-chunk
    const int gw   = (blockIdx.x << 2) + (threadIdx.x >> 5);
    const int nw   = gridDim.x << 2;
    const int nit  = NIT0 + g_nitems;

    for (int it = gw; it < nit; it += nw) {
        int start, count, node;
        bool use_perm;
        if (it < NIT0) { start = it * 8; count = 8; node = 0; use_perm = false; }
        else {
            const int2 t = g_items[it - NIT0];
            start = t.x & 0xffff; count = t.x >> 16; node = t.y;
            use_perm = true;
        }

        int shift;
        float* qdst;
        if (node == 0)      { shift = 10; qdst = g_q0; }
        else if (node < 33) { shift = 5;  qdst = g_q1; }
        else                { shift = 0;  qdst = g_q2; }

        // per-lane sample: lane s (<count) owns sample s; others clamp
        const int pos   = start + ((lane < count) ? lane : (count - 1));
        const int myidx = use_perm ? g_perm[pos] : pos;
        const int mylab = labels[myidx];

        // broadcast the 8 x row offsets to all lanes (once per item)
        int xo[8];
        #pragma unroll
        for (int s = 0; s < 8; s++)
            xo[s] = __shfl_sync(0xffffffffu, myidx, s) * NHID;

        const float* __restrict__ Wn = W + (size_t)node * WSLICE + cg * 4;

        u64 acc0[8], acc1[8];       // (c0,c1),(c2,c3) packed per sample
        #pragma unroll
        for (int s = 0; s < 8; s++) { acc0[s] = 0ull; acc1[s] = 0ull; }

        // software pipeline: W for iteration 0 preloaded
        ulonglong2 wv[4];
        #pragma unroll
        for (int j = 0; j < 4; j++)
            wv[j] = *(const ulonglong2*)&Wn[(hs * 4 + j) * BR];

        #pragma unroll 2
        for (int hb = 0; hb < NHID; hb += 16) {
            const int h0 = hb + hs * 4;

            // prefetch next iteration's W before the FMAs
            ulonglong2 wn[4];
            const bool more = (hb + 16) < NHID;
            #pragma unroll
            for (int j = 0; j < 4; j++)
                if (more) wn[j] = *(const ulonglong2*)&Wn[(h0 + 16 + j) * BR];

            // per-sample: load x, then its 8 fma2 — small live set,
            // chains across samples stay independent for MLP
            #pragma unroll
            for (int s = 0; s < 8; s++) {
                const float4 xv = *(const float4*)&inputs[xo[s] + h0];
                #pragma unroll
                for (int j = 0; j < 4; j++) {
                    const u64 xd = dup2((&xv.x)[j]);
                    acc0[s] = fma2(wv[j].x, xd, acc0[s]);
                    acc1[s] = fma2(wv[j].y, xd, acc1[s]);
                }
            }
            #pragma unroll
            for (int j = 0; j < 4; j++) wv[j] = wn[j];
        }

        // reduce over the 4 h-stripes (lanes cg, cg+8, cg+16, cg+24)
        #pragma unroll
        for (int o = 8; o <= 16; o <<= 1)
            #pragma unroll
            for (int s = 0; s < 8; s++) {
                acc0[s] = add2(acc0[s], __shfl_xor_sync(0xffffffffu, acc0[s], o));
                acc1[s] = add2(acc1[s], __shfl_xor_sync(0xffffffffu, acc1[s], o));
            }

        // per-sample softmax across the 8 column-group lanes
        #pragma unroll
        for (int s = 0; s < 8; s++) {
            const int st = (__shfl_sync(0xffffffffu, mylab, s) >> shift) & 31; // warp-uniform
            const float a0 = lo32(acc0[s]), a1 = hi32(acc0[s]);
            const float a2 = lo32(acc1[s]), a3 = hi32(acc1[s]);
            float mx = fmaxf(fmaxf(a0, a1), fmaxf(a2, a3));
            #pragma unroll
            for (int o = 1; o < 8; o <<= 1)
                mx = fmaxf(mx, __shfl_xor_sync(0xffffffffu, mx, o));
            float e = __expf(a0 - mx) + __expf(a1 - mx) + __expf(a2 - mx) + __expf(a3 - mx);
            #pragma unroll
            for (int o = 1; o < 8; o <<= 1)
                e += __shfl_xor_sync(0xffffffffu, e, o);
            const float lse = mx + __logf(e);
            // selected logit lives in lane (st>>2) of each 8-lane group
            const int r = st & 3;
            const float v = (r == 0) ? a0 : (r == 1) ? a1 : (r == 2) ? a2 : a3;
            const float sel = __shfl_sync(0xffffffffu, v, (lane & 24) | (st >> 2));
            if (lane == s && lane < count) qdst[myidx] = sel - lse;
        }
    }
}

// ================= combine + reset item counter for next replay ============
__global__ void hs_combine(float* __restrict__ out)
{
    int i = blockIdx.x * blockDim.x + threadIdx.x;   // 16 x 256
    out[i] = __expf(g_q0[i] + g_q1[i] + g_q2[i]);
    if (i == 0) g_nitems = 0;
}

} // namespace

extern "C" void kernel_launch(void* const* d_in, const int* in_sizes, int n_in,
                              void* d_out, int out_size)
{
    const float* inputs = (const float*)d_in[0];
    const int*   labels = (const int*)d_in[1];
    const float* W      = (const float*)d_in[2];
    float*       out    = (float*)d_out;

    hs_sort2  <<<32, 256>>>(labels);
    hs_main   <<<592, 128>>>(inputs, labels, W);
    hs_combine<<<16, 256>>>(out);
}